// round 13
// baseline (speedup 1.0000x reference)
#include <cuda_runtime.h>

#define NPIX 49
#define CH 96
#define HD 32
#define HW 56
#define BATCH 128
#define NWIN 8192
#define QKV_STRIDE 52                 // padded row stride in scratch
#define WIN_STRIDE (288 * QKV_STRIDE) // 14976 floats per window

// Pre-transposed weights: [c][m] so m-adjacent pairs are contiguous
__device__ float g_wq_t[CH * 3 * CH];   // 96 x 288
__device__ float g_wp_t[CH * CH];       // 96 x 96
// qkv scratch: [win][m 0..287][pix 0..48 (pad 52)]  (~490 MB)
__device__ float g_qkv[(size_t)NWIN * WIN_STRIDE];

__global__ void prep_kernel(const float* __restrict__ qkv_w,
                            const float* __restrict__ proj_w) {
    int t = blockIdx.x * blockDim.x + threadIdx.x;
    int stride = gridDim.x * blockDim.x;
    for (int i = t; i < 288 * 96; i += stride) {
        int m = i / 96, c = i % 96;
        g_wq_t[c * 288 + m] = qkv_w[i];
    }
    for (int i = t; i < 96 * 96; i += stride) {
        int m = i / 96, c = i % 96;
        g_wp_t[c * 96 + m] = proj_w[i];
    }
}

// ---- packed f32x2 helpers (dual-FMA on sm_103a; rounding identical to fmaf) ----
typedef unsigned long long u64;

__device__ __forceinline__ void fma2(u64& d, u64 a, u64 b) {
    asm("fma.rn.f32x2 %0, %1, %2, %0;" : "+l"(d) : "l"(a), "l"(b));
}
__device__ __forceinline__ u64 pack2(float lo, float hi) {
    u64 r;
    asm("mov.b64 %0, {%1, %2};" : "=l"(r) : "f"(lo), "f"(hi));
    return r;
}
__device__ __forceinline__ float2 unpack2(u64 v) {
    float2 r;
    asm("mov.b64 {%0, %1}, %2;" : "=f"(r.x), "=f"(r.y) : "l"(v));
    return r;
}

// Fast exp on the FMA pipe (avoids MUFU.EX2 throughput wall).
__device__ __forceinline__ float fexp(float x) {
    x = fmaxf(x, -87.0f);
    float n = rintf(x * 1.4426950408889634f);
    float r = fmaf(n, -0.6931471805599453f, x);
    float p = fmaf(r, 8.3333333e-3f, 4.1666667e-2f);
    p = fmaf(p, r, 0.16666667f);
    p = fmaf(p, r, 0.5f);
    p = fmaf(p, r, 1.0f);
    p = fmaf(p, r, 1.0f);
    int e = (int)n;
    return p * __int_as_float((e + 127) << 23);
}

// ============================================================================
// Kernel A: gather + LayerNorm + QKV GEMM -> g_qkv[win][m][52]
// 512 threads, <=64 regs, ~19 KB smem  => 2 CTAs/SM = 32 warps/SM
// ============================================================================
__global__ void __launch_bounds__(512, 2)
qkv_kernel(const float* __restrict__ x,
           const float* __restrict__ ln_g, const float* __restrict__ ln_b,
           const float* __restrict__ qkv_b) {
    __shared__ float sm[4802];   // x: [0,4704), mu: [4704,4753), rs: [4753,4802)
    float* sm_x  = sm;
    float* sm_mu = sm + 4704;
    float* sm_rs = sm + 4753;

    const int t   = threadIdx.x;
    const int win = blockIdx.x;
    const int b   = win >> 6;
    const int wr  = (win >> 3) & 7;
    const int wc  = win & 7;

    // gather x (roll -3) into smem [c][49]
    const float* xb = x + (size_t)b * CH * (HW * HW);
    for (int idx = t; idx < CH * NPIX; idx += 512) {
        int c = idx / NPIX, p = idx % NPIX;
        int pr = p / 7, pc = p % 7;
        int gh = wr * 7 + pr + 3; if (gh >= 56) gh -= 56;
        int gw = wc * 7 + pc + 3; if (gw >= 56) gw -= 56;
        sm_x[c * NPIX + p] = __ldg(xb + c * (HW * HW) + gh * HW + gw);
    }
    __syncthreads();
    if (t < NPIX) {
        float s = 0.f, ss = 0.f;
        #pragma unroll 8
        for (int c = 0; c < CH; ++c) {
            float v = sm_x[c * NPIX + t];
            s += v; ss += v * v;
        }
        float mu = s * (1.0f / 96.0f);
        float var = ss * (1.0f / 96.0f) - mu * mu;
        sm_mu[t] = mu;
        sm_rs[t] = rsqrtf(var + 1e-5f);
    }
    __syncthreads();
    for (int idx = t; idx < CH * NPIX; idx += 512) {
        int c = idx / NPIX, p = idx % NPIX;
        sm_x[idx] = (sm_x[idx] - sm_mu[p]) * sm_rs[p] * __ldg(ln_g + c) + __ldg(ln_b + c);
    }
    __syncthreads();

    // GEMM 288m x 49p, K=96; 4m x 7p tiles on 504 threads
    if (t < 504) {
        const int mg = t / 7, pg = t % 7;
        const int m0 = mg * 4, p0 = pg * 7;
        u64 acc[2][7];
        #pragma unroll
        for (int a = 0; a < 2; ++a)
            #pragma unroll
            for (int pi = 0; pi < 7; ++pi) acc[a][pi] = 0ull;
        const float* wb = g_wq_t + m0;     // 16B-aligned (m0 % 4 == 0)
        const float* xr0 = sm_x + p0;
        #pragma unroll 2
        for (int c = 0; c < CH; ++c) {
            ulonglong2 wa = __ldg((const ulonglong2*)(wb + c * 288));
            u64 wp0 = wa.x, wp1 = wa.y;
            const float* xr = xr0 + c * NPIX;
            #pragma unroll
            for (int pi = 0; pi < 7; ++pi) {
                float xv = xr[pi];
                u64 xx = pack2(xv, xv);
                fma2(acc[0][pi], wp0, xx);
                fma2(acc[1][pi], wp1, xx);
            }
        }
        float* dst = g_qkv + (size_t)win * WIN_STRIDE;
        #pragma unroll
        for (int a = 0; a < 2; ++a) {
            float b0 = __ldg(qkv_b + m0 + 2 * a);
            float b1 = __ldg(qkv_b + m0 + 2 * a + 1);
            float* r0 = dst + (m0 + 2 * a) * QKV_STRIDE + p0;
            float* r1 = dst + (m0 + 2 * a + 1) * QKV_STRIDE + p0;
            #pragma unroll
            for (int pi = 0; pi < 7; ++pi) {
                float2 u = unpack2(acc[a][pi]);
                r0[pi] = u.x + b0;
                r1[pi] = u.y + b1;
            }
        }
    }
}

// ============================================================================
// Kernel B: stage qkv + QK^T + softmax + AV + proj + scatter (R5 phases 2-5)
// smem layout (floats):
//   sm_qkv : [0, 14112)   rows [m][49]: q m<96, k 96..191, v 192..287
//   sm_att : [0, 7203)    aliases q + k-head after phase-2a barrier
//   sm_av  : [14112, 18816)  fresh region (disjoint from att and v)
//   sm_lab : [18816, 18865)
// ============================================================================
#define SMEMB_FLOATS 18880

extern __shared__ float smemb[];

__global__ void __launch_bounds__(256, 3)
attn_kernel(const float* __restrict__ proj_b,
            const float* __restrict__ rel_table,
            float* __restrict__ out) {
    float* sm_qkv = smemb;
    float* sm_att = smemb;            // valid after phase-2a barrier
    float* sm_av  = smemb + 14112;
    int*   sm_lab = (int*)(smemb + 18816);

    const int t   = threadIdx.x;
    const int win = blockIdx.x;
    const int b   = win >> 6;
    const int wr  = (win >> 3) & 7;
    const int wc  = win & 7;

    // labels + stage qkv from scratch
    if (t < NPIX) {
        int pr = t / 7, pc = t % 7;
        int hs = wr * 7 + pr, wsv = wc * 7 + pc;
        int lh = hs < 49 ? 0 : (hs < 53 ? 1 : 2);
        int lw = wsv < 49 ? 0 : (wsv < 53 ? 1 : 2);
        sm_lab[t] = lh * 3 + lw;
    }
    const float* src = g_qkv + (size_t)win * WIN_STRIDE;
    for (int idx = t; idx < 288 * NPIX; idx += 256) {
        int m = idx / NPIX, p = idx - m * NPIX;
        sm_qkv[idx] = __ldg(src + m * QKV_STRIDE + p);
    }
    __syncthreads();

    // ---- Phase 2a: QK^T into registers (147 threads, packed over i) ----
    u64 acc2[3][7];
    float acc6[7];
    int h = 0, ig = 0, jg = 0;
    if (t < 147) {
        h = t / 49;
        int r = t % 49;
        ig = r / 7; jg = r % 7;
        const int i0 = ig * 7, j0 = jg * 7;
        #pragma unroll
        for (int a = 0; a < 3; ++a)
            #pragma unroll
            for (int jj = 0; jj < 7; ++jj) acc2[a][jj] = 0ull;
        #pragma unroll
        for (int jj = 0; jj < 7; ++jj) acc6[jj] = 0.f;
        const float* qb = sm_qkv + (h * HD) * NPIX;
        const float* kb = sm_qkv + ((CH + h * HD)) * NPIX;
        for (int d = 0; d < HD; ++d) {
            float qv[7], kv[7];
            #pragma unroll
            for (int k = 0; k < 7; ++k) {
                qv[k] = qb[d * NPIX + i0 + k];
                kv[k] = kb[d * NPIX + j0 + k];
            }
            u64 qp[3];
            #pragma unroll
            for (int a = 0; a < 3; ++a) qp[a] = pack2(qv[2 * a], qv[2 * a + 1]);
            #pragma unroll
            for (int jj = 0; jj < 7; ++jj) {
                u64 kk = pack2(kv[jj], kv[jj]);
                #pragma unroll
                for (int a = 0; a < 3; ++a) fma2(acc2[a][jj], qp[a], kk);
                acc6[jj] = fmaf(qv[6], kv[jj], acc6[jj]);
            }
        }
    }
    __syncthreads();   // q, k dead -> attn may overwrite [0, 7203)

    // ---- Phase 2b: scale + rel bias + shift mask -> attn ----
    if (t < 147) {
        const int i0 = ig * 7, j0 = jg * 7;
        const float scale = 0.17677669529663687f;  // 1/sqrt(32)
        #pragma unroll
        for (int ii = 0; ii < 7; ++ii) {
            int i = i0 + ii;
            int li = sm_lab[i];
            #pragma unroll
            for (int jj = 0; jj < 7; ++jj) {
                int j = j0 + jj;
                float val;
                if (ii == 6) val = acc6[jj];
                else {
                    float2 u = unpack2(acc2[ii >> 1][jj]);
                    val = (ii & 1) ? u.y : u.x;
                }
                int idx = (ig - jg + 6) * 13 + (ii - jj + 6);
                float bias = __ldg(rel_table + idx * 3 + h);
                float msk = (li == sm_lab[j]) ? 0.f : -100.f;
                sm_att[(h * 49 + i) * 49 + j] = fmaf(val, scale, bias + msk);
            }
        }
    }
    __syncthreads();

    // ---- Phase 3: softmax over j ----
    if (t < 147) {
        float* row = sm_att + t * 49;
        float mx = -1e30f;
        #pragma unroll 7
        for (int j = 0; j < 49; ++j) mx = fmaxf(mx, row[j]);
        float s = 0.f;
        #pragma unroll 7
        for (int j = 0; j < 49; ++j) {
            float e = fexp(row[j] - mx);
            row[j] = e; s += e;
        }
        float inv = 1.0f / s;
        #pragma unroll 7
        for (int j = 0; j < 49; ++j) row[j] *= inv;
    }
    __syncthreads();

    // ---- Phase 4: AV (96 x 49, K=49), 4m x 7p tiles; av -> fresh region ----
    if (t < 168) {
        const int mg = t / 7, pg = t % 7;
        const int m0 = mg * 4, p0 = pg * 7;
        const int hh = m0 >> 5;
        u64 acc[2][7];
        #pragma unroll
        for (int a = 0; a < 2; ++a)
            #pragma unroll
            for (int pi = 0; pi < 7; ++pi) acc[a][pi] = 0ull;
        const float* vb = sm_qkv + (2 * CH + m0) * NPIX;
        const float* ab = sm_att + (hh * 49 + p0) * 49;
        for (int j = 0; j < 49; ++j) {
            u64 vp[2];
            vp[0] = pack2(vb[0 * NPIX + j], vb[1 * NPIX + j]);
            vp[1] = pack2(vb[2 * NPIX + j], vb[3 * NPIX + j]);
            #pragma unroll
            for (int pi = 0; pi < 7; ++pi) {
                float av = ab[pi * 49 + j];
                u64 ap = pack2(av, av);
                fma2(acc[0][pi], vp[0], ap);
                fma2(acc[1][pi], vp[1], ap);
            }
        }
        #pragma unroll
        for (int a = 0; a < 2; ++a)
            #pragma unroll
            for (int pi = 0; pi < 7; ++pi) {
                float2 u = unpack2(acc[a][pi]);
                sm_av[(m0 + 2 * a) * NPIX + p0 + pi]     = u.x;
                sm_av[(m0 + 2 * a + 1) * NPIX + p0 + pi] = u.y;
            }
    }
    __syncthreads();

    // ---- Phase 5: proj GEMM (96 x 49, K=96) + scatter (roll +3) ----
    if (t < 168) {
        const int mg = t / 7, pg = t % 7;
        const int m0 = mg * 4, p0 = pg * 7;
        u64 acc[2][7];
        #pragma unroll
        for (int a = 0; a < 2; ++a)
            #pragma unroll
            for (int pi = 0; pi < 7; ++pi) acc[a][pi] = 0ull;
        const float* wb = g_wp_t + m0;          // 16B-aligned
        const float* xr0 = sm_av + p0;
        #pragma unroll 4
        for (int c = 0; c < CH; ++c) {
            ulonglong2 wa = __ldg((const ulonglong2*)(wb + c * 96));
            u64 wp[2] = {wa.x, wa.y};
            const float* xr = xr0 + c * NPIX;
            #pragma unroll
            for (int pi = 0; pi < 7; ++pi) {
                float xv = xr[pi];
                u64 xx = pack2(xv, xv);
                fma2(acc[0][pi], wp[0], xx);
                fma2(acc[1][pi], wp[1], xx);
            }
        }
        float* ob = out + (size_t)b * CH * (HW * HW);
        int gh = wr * 7 + pg + 3; if (gh >= 56) gh -= 56;
        #pragma unroll
        for (int a = 0; a < 2; ++a) {
            float b0 = __ldg(proj_b + m0 + 2 * a);
            float b1 = __ldg(proj_b + m0 + 2 * a + 1);
            float* orow0 = ob + (m0 + 2 * a) * (HW * HW) + gh * HW;
            float* orow1 = ob + (m0 + 2 * a + 1) * (HW * HW) + gh * HW;
            #pragma unroll
            for (int pi = 0; pi < 7; ++pi) {
                int gw = wc * 7 + pi + 3; if (gw >= 56) gw -= 56;
                float2 u = unpack2(acc[a][pi]);
                orow0[gw] = u.x + b0;
                orow1[gw] = u.y + b1;
            }
        }
    }
}

extern "C" void kernel_launch(void* const* d_in, const int* in_sizes, int n_in,
                              void* d_out, int out_size) {
    const float* x      = (const float*)d_in[0];
    const float* ln_g   = (const float*)d_in[1];
    const float* ln_b   = (const float*)d_in[2];
    const float* qkv_w  = (const float*)d_in[3];
    const float* qkv_b  = (const float*)d_in[4];
    const float* proj_w = (const float*)d_in[5];
    const float* proj_b = (const float*)d_in[6];
    const float* rel    = (const float*)d_in[7];
    float* out = (float*)d_out;

    cudaFuncSetAttribute(attn_kernel, cudaFuncAttributeMaxDynamicSharedMemorySize,
                         SMEMB_FLOATS * (int)sizeof(float));

    prep_kernel<<<64, 256>>>(qkv_w, proj_w);
    qkv_kernel<<<NWIN, 512>>>(x, ln_g, ln_b, qkv_b);
    attn_kernel<<<NWIN, 256, SMEMB_FLOATS * sizeof(float)>>>(proj_b, rel, out);
}

// round 14
// speedup vs baseline: 1.2374x; 1.2374x over previous
#include <cuda_runtime.h>

#define NPIX 49
#define CH 96
#define HD 32
#define HW 56
#define BATCH 128

// Pre-transposed weights: [c][m] so m-adjacent pairs are contiguous
__device__ float g_wq_t[CH * 3 * CH];   // 96 x 288
__device__ float g_wp_t[CH * CH];       // 96 x 96

__global__ void prep_kernel(const float* __restrict__ qkv_w,
                            const float* __restrict__ proj_w) {
    int t = blockIdx.x * blockDim.x + threadIdx.x;
    int stride = gridDim.x * blockDim.x;
    for (int i = t; i < 288 * 96; i += stride) {
        int m = i / 96, c = i % 96;
        g_wq_t[c * 288 + m] = qkv_w[i];
    }
    for (int i = t; i < 96 * 96; i += stride) {
        int m = i / 96, c = i % 96;
        g_wp_t[c * 96 + m] = proj_w[i];
    }
}

// ---- packed f32x2 helpers (dual-FMA on sm_103a; rounding identical to fmaf) ----
typedef unsigned long long u64;

__device__ __forceinline__ void fma2(u64& d, u64 a, u64 b) {
    asm("fma.rn.f32x2 %0, %1, %2, %0;" : "+l"(d) : "l"(a), "l"(b));
}
__device__ __forceinline__ u64 pack2(float lo, float hi) {
    u64 r;
    asm("mov.b64 %0, {%1, %2};" : "=l"(r) : "f"(lo), "f"(hi));
    return r;
}
__device__ __forceinline__ float2 unpack2(u64 v) {
    float2 r;
    asm("mov.b64 {%0, %1}, %2;" : "=f"(r.x), "=f"(r.y) : "l"(v));
    return r;
}

// Fast exp on the FMA pipe (avoids MUFU.EX2 throughput wall).
__device__ __forceinline__ float fexp(float x) {
    x = fmaxf(x, -87.0f);
    float n = rintf(x * 1.4426950408889634f);
    float r = fmaf(n, -0.6931471805599453f, x);
    float p = fmaf(r, 8.3333333e-3f, 4.1666667e-2f);
    p = fmaf(p, r, 0.16666667f);
    p = fmaf(p, r, 0.5f);
    p = fmaf(p, r, 1.0f);
    p = fmaf(p, r, 1.0f);
    int e = (int)n;
    return p * __int_as_float((e + 127) << 23);
}

// Shared memory layout (floats) — liveness-aliased to fit 3 CTAs/SM:
//  sm_k   : [0, 4704)       k rows;    also: LN partials [0,392) pre-phase1; after ph4: AV out
//  sm_v   : [4704, 9408)    v rows
//  sm_q   : [9408, 14112)   q rows;    after ph2a: attn (part)
//  sm_x   : [14112, 18816)  xn;        after ph2a: attn (rest)
//  attn   : [9408, 16611)   3*49*49 = 7203 floats
//  sm_mu  : [18816, 18865)
//  sm_rs  : [18865, 18914)
//  sm_lab : [18914, 18963)
#define SMEM_FLOATS 18963

extern __shared__ float smem[];

__global__ void __launch_bounds__(256, 3)
swin_kernel(const float* __restrict__ x,
            const float* __restrict__ ln_g, const float* __restrict__ ln_b,
            const float* __restrict__ qkv_b,
            const float* __restrict__ proj_b,
            const float* __restrict__ rel_table,
            float* __restrict__ out) {
    float* sm_k   = smem;
    float* sm_v   = smem + 4704;
    float* sm_q   = smem + 9408;
    float* sm_x   = smem + 14112;
    float* sm_att = smem + 9408;    // aliases q + x after phase-2a
    float* sm_av  = smem;           // aliases k after phase 4
    float* sm_mu  = smem + 18816;
    float* sm_rs  = smem + 18865;
    int*   sm_lab = (int*)(smem + 18914);

    const int t  = threadIdx.x;
    const int wid = blockIdx.x;
    const int b  = wid >> 6;
    const int wr = (wid >> 3) & 7;
    const int wc = wid & 7;

    // ---- Phase 0: labels, gather x (roll -3), parallel LN ----
    if (t < NPIX) {
        int pr = t / 7, pc = t % 7;
        int hs = wr * 7 + pr, wsv = wc * 7 + pc;
        int lh = hs < 49 ? 0 : (hs < 53 ? 1 : 2);
        int lw = wsv < 49 ? 0 : (wsv < 53 ? 1 : 2);
        sm_lab[t] = lh * 3 + lw;
    }
    const float* xb = x + (size_t)b * CH * (HW * HW);
    for (int idx = t; idx < CH * NPIX; idx += 256) {
        int c = idx / NPIX, p = idx % NPIX;
        int pr = p / 7, pc = p % 7;
        int gh = wr * 7 + pr + 3; if (gh >= 56) gh -= 56;
        int gw = wc * 7 + pc + 3; if (gw >= 56) gw -= 56;
        sm_x[c * NPIX + p] = __ldg(xb + c * (HW * HW) + gh * HW + gw);
    }
    __syncthreads();
    // partial sums: 196 threads, 24 channels each -> k region (not yet live)
    if (t < 196) {
        int p = t % 49, cq = t / 49;
        float s = 0.f, ss = 0.f;
        #pragma unroll
        for (int c = cq * 24; c < cq * 24 + 24; ++c) {
            float v = sm_x[c * NPIX + p];
            s += v; ss += v * v;
        }
        smem[t] = s;            // partials [0,196)
        smem[196 + t] = ss;     // partials [196,392)
    }
    __syncthreads();
    if (t < NPIX) {
        float s  = (smem[t] + smem[49 + t]) + (smem[98 + t] + smem[147 + t]);
        float ss = (smem[196 + t] + smem[245 + t]) + (smem[294 + t] + smem[343 + t]);
        float mu = s * (1.0f / 96.0f);
        float var = ss * (1.0f / 96.0f) - mu * mu;
        sm_mu[t] = mu;
        sm_rs[t] = rsqrtf(var + 1e-5f);
    }
    __syncthreads();
    for (int idx = t; idx < CH * NPIX; idx += 256) {
        int c = idx / NPIX, p = idx % NPIX;
        int a = c * NPIX + p;
        sm_x[a] = (sm_x[a] - sm_mu[p]) * sm_rs[p] * __ldg(ln_g + c) + __ldg(ln_b + c);
    }
    __syncthreads();

    // ---- Phase 1: QKV GEMM (288 x 49, K=96), 8m x 7p tiles, weights via __ldg ----
    if (t < 252) {
        const int mg = t / 7, pg = t % 7;
        const int m0 = mg * 8, p0 = pg * 7;
        u64 acc[4][7];
        #pragma unroll
        for (int a = 0; a < 4; ++a)
            #pragma unroll
            for (int pi = 0; pi < 7; ++pi) acc[a][pi] = 0ull;
        const float* wb = g_wq_t + m0;         // 32B-aligned (m0 % 8 == 0)
        const float* xr0 = sm_x + p0;
        #pragma unroll 4
        for (int c = 0; c < CH; ++c) {
            ulonglong2 wa = __ldg((const ulonglong2*)(wb + c * 288));
            ulonglong2 wc2 = __ldg((const ulonglong2*)(wb + c * 288) + 1);
            u64 wp[4] = {wa.x, wa.y, wc2.x, wc2.y};
            const float* xr = xr0 + c * NPIX;
            #pragma unroll
            for (int pi = 0; pi < 7; ++pi) {
                float xv = xr[pi];
                u64 xx = pack2(xv, xv);
                #pragma unroll
                for (int a = 0; a < 4; ++a)
                    fma2(acc[a][pi], wp[a], xx);
            }
        }
        float* dst = (m0 < 96) ? (sm_q + m0 * NPIX)
                   : (m0 < 192) ? (sm_k + (m0 - 96) * NPIX)
                   : (sm_v + (m0 - 192) * NPIX);
        #pragma unroll
        for (int a = 0; a < 4; ++a) {
            float b0 = __ldg(qkv_b + m0 + 2 * a);
            float b1 = __ldg(qkv_b + m0 + 2 * a + 1);
            #pragma unroll
            for (int pi = 0; pi < 7; ++pi) {
                float2 u = unpack2(acc[a][pi]);
                dst[(2 * a) * NPIX + p0 + pi]     = u.x + b0;
                dst[(2 * a + 1) * NPIX + p0 + pi] = u.y + b1;
            }
        }
    }
    __syncthreads();

    // ---- Phase 2a: QK^T into registers (147 threads, packed over i) ----
    u64 acc2[3][7];
    float acc6[7];
    int h = 0, ig = 0, jg = 0;
    if (t < 147) {
        h = t / 49;
        int r = t % 49;
        ig = r / 7; jg = r % 7;
        const int i0 = ig * 7, j0 = jg * 7;
        #pragma unroll
        for (int a = 0; a < 3; ++a)
            #pragma unroll
            for (int jj = 0; jj < 7; ++jj) acc2[a][jj] = 0ull;
        #pragma unroll
        for (int jj = 0; jj < 7; ++jj) acc6[jj] = 0.f;
        const float* qb = sm_q + (h * HD) * NPIX;
        const float* kb = sm_k + (h * HD) * NPIX;
        for (int d = 0; d < HD; ++d) {
            float qv[7], kv[7];
            #pragma unroll
            for (int k = 0; k < 7; ++k) {
                qv[k] = qb[d * NPIX + i0 + k];
                kv[k] = kb[d * NPIX + j0 + k];
            }
            u64 qp[3];
            #pragma unroll
            for (int a = 0; a < 3; ++a) qp[a] = pack2(qv[2 * a], qv[2 * a + 1]);
            #pragma unroll
            for (int jj = 0; jj < 7; ++jj) {
                u64 kk = pack2(kv[jj], kv[jj]);
                #pragma unroll
                for (int a = 0; a < 3; ++a) fma2(acc2[a][jj], qp[a], kk);
                acc6[jj] = fmaf(qv[6], kv[jj], acc6[jj]);
            }
        }
    }
    __syncthreads();   // q, k, x now dead -> attn may overwrite [9408, 16611)

    // ---- Phase 2b: scale + rel bias + shift mask -> attn ----
    if (t < 147) {
        const int i0 = ig * 7, j0 = jg * 7;
        const float scale = 0.17677669529663687f;  // 1/sqrt(32)
        #pragma unroll
        for (int ii = 0; ii < 7; ++ii) {
            int i = i0 + ii;
            int li = sm_lab[i];
            #pragma unroll
            for (int jj = 0; jj < 7; ++jj) {
                int j = j0 + jj;
                float val;
                if (ii == 6) val = acc6[jj];
                else {
                    float2 u = unpack2(acc2[ii >> 1][jj]);
                    val = (ii & 1) ? u.y : u.x;
                }
                int idx = (ig - jg + 6) * 13 + (ii - jj + 6);
                float bias = __ldg(rel_table + idx * 3 + h);
                float msk = (li == sm_lab[j]) ? 0.f : -100.f;
                sm_att[(h * 49 + i) * 49 + j] = fmaf(val, scale, bias + msk);
            }
        }
    }
    __syncthreads();

    // ---- Phase 3: softmax over j ----
    if (t < 147) {
        float* row = sm_att + t * 49;
        float mx = -1e30f;
        #pragma unroll 7
        for (int j = 0; j < 49; ++j) mx = fmaxf(mx, row[j]);
        float s = 0.f;
        #pragma unroll 7
        for (int j = 0; j < 49; ++j) {
            float e = fexp(row[j] - mx);
            row[j] = e; s += e;
        }
        float inv = 1.0f / s;
        #pragma unroll 7
        for (int j = 0; j < 49; ++j) row[j] *= inv;
    }
    __syncthreads();

    // ---- Phase 4: AV (96 x 49, K=49), 4m x 7p tiles; out -> dead k region ----
    if (t < 168) {
        const int mg = t / 7, pg = t % 7;
        const int m0 = mg * 4, p0 = pg * 7;
        const int hh = m0 >> 5;
        u64 acc[2][7];
        #pragma unroll
        for (int a = 0; a < 2; ++a)
            #pragma unroll
            for (int pi = 0; pi < 7; ++pi) acc[a][pi] = 0ull;
        const float* vb = sm_v + m0 * NPIX;
        const float* ab = sm_att + (hh * 49 + p0) * 49;
        for (int j = 0; j < 49; ++j) {
            u64 vp[2];
            vp[0] = pack2(vb[0 * NPIX + j], vb[1 * NPIX + j]);
            vp[1] = pack2(vb[2 * NPIX + j], vb[3 * NPIX + j]);
            #pragma unroll
            for (int pi = 0; pi < 7; ++pi) {
                float av = ab[pi * 49 + j];
                u64 ap = pack2(av, av);
                fma2(acc[0][pi], vp[0], ap);
                fma2(acc[1][pi], vp[1], ap);
            }
        }
        #pragma unroll
        for (int a = 0; a < 2; ++a)
            #pragma unroll
            for (int pi = 0; pi < 7; ++pi) {
                float2 u = unpack2(acc[a][pi]);
                sm_av[(m0 + 2 * a) * NPIX + p0 + pi]     = u.x;
                sm_av[(m0 + 2 * a + 1) * NPIX + p0 + pi] = u.y;
            }
    }
    __syncthreads();

    // ---- Phase 5: proj GEMM (96 x 49, K=96) + scatter (roll +3) ----
    if (t < 168) {
        const int mg = t / 7, pg = t % 7;
        const int m0 = mg * 4, p0 = pg * 7;
        u64 acc[2][7];
        #pragma unroll
        for (int a = 0; a < 2; ++a)
            #pragma unroll
            for (int pi = 0; pi < 7; ++pi) acc[a][pi] = 0ull;
        const float* wb = g_wp_t + m0;          // 16B-aligned (m0 % 4 == 0)
        const float* xr0 = sm_av + p0;
        #pragma unroll 8
        for (int c = 0; c < CH; ++c) {
            ulonglong2 wa = __ldg((const ulonglong2*)(wb + c * 96));
            u64 wp[2] = {wa.x, wa.y};
            const float* xr = xr0 + c * NPIX;
            #pragma unroll
            for (int pi = 0; pi < 7; ++pi) {
                float xv = xr[pi];
                u64 xx = pack2(xv, xv);
                fma2(acc[0][pi], wp[0], xx);
                fma2(acc[1][pi], wp[1], xx);
            }
        }
        float* ob = out + (size_t)b * CH * (HW * HW);
        int gh = wr * 7 + pg + 3; if (gh >= 56) gh -= 56;
        #pragma unroll
        for (int a = 0; a < 2; ++a) {
            float b0 = __ldg(proj_b + m0 + 2 * a);
            float b1 = __ldg(proj_b + m0 + 2 * a + 1);
            float* orow0 = ob + (m0 + 2 * a) * (HW * HW) + gh * HW;
            float* orow1 = ob + (m0 + 2 * a + 1) * (HW * HW) + gh * HW;
            #pragma unroll
            for (int pi = 0; pi < 7; ++pi) {
                int gw = wc * 7 + pi + 3; if (gw >= 56) gw -= 56;
                float2 u = unpack2(acc[a][pi]);
                orow0[gw] = u.x + b0;
                orow1[gw] = u.y + b1;
            }
        }
    }
}

extern "C" void kernel_launch(void* const* d_in, const int* in_sizes, int n_in,
                              void* d_out, int out_size) {
    const float* x      = (const float*)d_in[0];
    const float* ln_g   = (const float*)d_in[1];
    const float* ln_b   = (const float*)d_in[2];
    const float* qkv_w  = (const float*)d_in[3];
    const float* qkv_b  = (const float*)d_in[4];
    const float* proj_w = (const float*)d_in[5];
    const float* proj_b = (const float*)d_in[6];
    const float* rel    = (const float*)d_in[7];
    float* out = (float*)d_out;

    cudaFuncSetAttribute(swin_kernel, cudaFuncAttributeMaxDynamicSharedMemorySize,
                         SMEM_FLOATS * (int)sizeof(float));

    prep_kernel<<<64, 256>>>(qkv_w, proj_w);
    swin_kernel<<<BATCH * 64, 256, SMEM_FLOATS * sizeof(float)>>>(
        x, ln_g, ln_b, qkv_b, proj_b, rel, out);
}